// round 9
// baseline (speedup 1.0000x reference)
#include <cuda_runtime.h>

#define B_   32
#define T_   64
#define E_   512
#define H_   1024
#define V_   32000
#define G3_  3072
#define SOS_ 1
#define SPLITK 3
#define NJ_GATES  24

// ---------------- persistent device state ----------------
__device__ float g_h0T[2][H_*B_];            // layer-0 hidden, transposed [k][b], ping-pong
__device__ float g_h1T[2][H_*B_];            // layer-1 hidden
__device__ float g_giP[SPLITK][G3_*B_];      // split-K partials x@W_ih^T, layout [j][b]
__device__ float g_ghP[SPLITK][G3_*B_];      // split-K partials h@W_hh^T
__device__ unsigned long long g_argmax[B_];  // packed (orderable_val<<32 | ~index)

__device__ __forceinline__ float* hbuf(int code){
    switch(code){
        case 0:  return g_h0T[0];
        case 1:  return g_h0T[1];
        case 2:  return g_h1T[0];
        default: return g_h1T[1];
    }
}

// packed f32x2 FMA — full-rate fp32 on sm_103a
#define PACK2(dst, f)      asm("mov.b64 %0, {%1, %1};" : "=l"(dst) : "f"(f))
#define FFMA2(acc, a, w)   asm("fma.rn.f32x2 %0, %1, %2, %0;" : "+l"(acc) : "l"(a), "l"(w))
#define UNPACK2(lo, hi, v) asm("mov.b64 {%0, %1}, %2;" : "=f"(lo), "=f"(hi) : "l"(v))

__device__ __forceinline__ unsigned long long packv(float f, unsigned v){
    unsigned u = __float_as_uint(f);
    u = (u & 0x80000000u) ? ~u : (u | 0x80000000u);   // monotonic order-preserving map
    return ((unsigned long long)u << 32) | (unsigned long long)(0xFFFFFFFFu - v);
}

// =============================================================================
// Gates GEMM: out[j][b] = sum_k W[j,k] * a[k][b].  One grid covers both gi and
// gh with split-K=3.  Tile 32b x 128j, 256 thr, thread = 8b x 2j, FFMA2 inner.
// =============================================================================
__global__ __launch_bounds__(256) void k_gates(
    const float* __restrict__ Wi, int Ki, int code_ai, int gather, int t,
    const float* __restrict__ Wh, int code_ah,
    const float* __restrict__ emb)
{
    __shared__ float w_s[32][129];
    __shared__ float a_s[32][32];
    __shared__ int   tok_s[B_];

    const int bid   = blockIdx.x;
    const int is_gh = (bid >= NJ_GATES*SPLITK);
    const int rem   = is_gh ? bid - NJ_GATES*SPLITK : bid;
    const int s     = rem / NJ_GATES;
    const int j0    = (rem % NJ_GATES) * 128;

    const float* W  = is_gh ? Wh : Wi;
    const int    K  = is_gh ? H_ : Ki;
    float*       out = is_gh ? g_ghP[s] : g_giP[s];
    const float* aT  = hbuf(is_gh ? code_ah : code_ai);
    const bool do_gather = (gather && !is_gh);

    const int TK  = K >> 5;
    const int kt0 = (TK * s) / SPLITK;
    const int kt1 = (TK * (s+1)) / SPLITK;

    const int tid = threadIdx.x;
    const int tvv = tid & 63, b0 = (tid >> 6) * 8;
    const int jr  = tid >> 1, half = tid & 1;

    if (do_gather){
        if (tid < B_){
            int tk = SOS_;
            if (t > 0) tk = (int)(0xFFFFFFFFu - (unsigned)(g_argmax[tid] & 0xFFFFFFFFull));
            tok_s[tid] = tk;
        }
        __syncthreads();
    }

    unsigned long long acc[2][4];
    #pragma unroll
    for (int i=0;i<2;i++){ acc[i][0]=0; acc[i][1]=0; acc[i][2]=0; acc[i][3]=0; }

    for (int kt = kt0; kt < kt1; kt++){
        const int kb = kt * 32;
        if (do_gather){
            int b = tid & 31, e0 = (tid >> 5) * 4;
            const float4 v = *(const float4*)(emb + (size_t)tok_s[b]*E_ + kb + e0);
            a_s[e0][b]=v.x; a_s[e0+1][b]=v.y; a_s[e0+2][b]=v.z; a_s[e0+3][b]=v.w;
        } else {
            *(float4*)((float*)a_s + tid*4) = *(const float4*)(aT + (size_t)kb*B_ + tid*4);
        }
        const float* wrow = W + (size_t)(j0 + jr)*K + kb + half*16;
        #pragma unroll
        for (int c=0;c<4;c++){
            float4 v = *(const float4*)(wrow + 4*c);
            int kk = half*16 + 4*c;
            w_s[kk][jr]=v.x; w_s[kk+1][jr]=v.y; w_s[kk+2][jr]=v.z; w_s[kk+3][jr]=v.w;
        }
        __syncthreads();
        #pragma unroll
        for (int k=0;k<32;k++){
            ulonglong2 A0 = *(const ulonglong2*)(&a_s[k][b0]);
            ulonglong2 A1 = *(const ulonglong2*)(&a_s[k][b0+4]);
            unsigned long long W0, W1;
            PACK2(W0, w_s[k][tvv]);
            PACK2(W1, w_s[k][tvv+64]);
            FFMA2(acc[0][0], A0.x, W0); FFMA2(acc[0][1], A0.y, W0);
            FFMA2(acc[0][2], A1.x, W0); FFMA2(acc[0][3], A1.y, W0);
            FFMA2(acc[1][0], A0.x, W1); FFMA2(acc[1][1], A0.y, W1);
            FFMA2(acc[1][2], A1.x, W1); FFMA2(acc[1][3], A1.y, W1);
        }
        __syncthreads();
    }
    #pragma unroll
    for (int i=0;i<2;i++){
        int j = j0 + tvv + 64*i;
        float o[8];
        #pragma unroll
        for (int q=0;q<4;q++) UNPACK2(o[2*q], o[2*q+1], acc[i][q]);
        *(float4*)(out + (size_t)j*B_ + b0    ) = make_float4(o[0],o[1],o[2],o[3]);
        *(float4*)(out + (size_t)j*B_ + b0 + 4) = make_float4(o[4],o[5],o[6],o[7]);
    }
}

// =============================================================================
// GRU combine: h_new = (1-z)*n + z*h   (sums split-K partials)
// =============================================================================
__global__ __launch_bounds__(256) void k_combine(
    const float* __restrict__ bih, const float* __restrict__ bhh,
    int code_old, int code_new, int reset)
{
    int idx = blockIdx.x*256 + threadIdx.x;   // 0..32767
    int b = idx & 31, k = idx >> 5;
    float gr=0.f, gz=0.f, gn=0.f, hr=0.f, hz=0.f, hn=0.f;
    #pragma unroll
    for (int s=0;s<SPLITK;s++){
        gr += g_giP[s][(size_t)k*B_ + b];
        gz += g_giP[s][(size_t)(H_  +k)*B_ + b];
        gn += g_giP[s][(size_t)(2*H_+k)*B_ + b];
        hr += g_ghP[s][(size_t)k*B_ + b];
        hz += g_ghP[s][(size_t)(H_  +k)*B_ + b];
        hn += g_ghP[s][(size_t)(2*H_+k)*B_ + b];
    }
    float r = 1.f/(1.f + expf(-(gr + bih[k]     + hr + bhh[k])));
    float z = 1.f/(1.f + expf(-(gz + bih[H_+k]  + hz + bhh[H_+k])));
    float n = tanhf(gn + bih[2*H_+k] + r*(hn + bhh[2*H_+k]));
    float h = hbuf(code_old)[(size_t)k*B_ + b];
    hbuf(code_new)[(size_t)k*B_ + b] = (1.f - z)*n + z*h;
    if (reset && idx < B_) g_argmax[idx] = 0ULL;
}

// =============================================================================
// Logits GEMM + bias + fused per-batch argmax.  250 blocks x 256 thr.
// =============================================================================
__global__ __launch_bounds__(256) void k_logits(
    const float* __restrict__ W, const float* __restrict__ bout,
    int code_h, float* __restrict__ out, int t)
{
    __shared__ float w_s[32][129];
    __shared__ float a_s[32][32];
    __shared__ unsigned long long red[B_][65];

    const float* aT = hbuf(code_h);
    const int j0  = blockIdx.x * 128;
    const int tid = threadIdx.x;
    const int tvv = tid & 63, b0 = (tid >> 6) * 8;
    const int jr  = tid >> 1, half = tid & 1;

    unsigned long long acc[2][4];
    #pragma unroll
    for (int i=0;i<2;i++){ acc[i][0]=0; acc[i][1]=0; acc[i][2]=0; acc[i][3]=0; }

    for (int kt=0; kt<H_/32; kt++){
        const int kb = kt*32;
        *(float4*)((float*)a_s + tid*4) = *(const float4*)(aT + (size_t)kb*B_ + tid*4);
        const float* wrow = W + (size_t)(j0 + jr)*H_ + kb + half*16;
        #pragma unroll
        for (int c=0;c<4;c++){
            float4 v = *(const float4*)(wrow + 4*c);
            int kk = half*16 + 4*c;
            w_s[kk][jr]=v.x; w_s[kk+1][jr]=v.y; w_s[kk+2][jr]=v.z; w_s[kk+3][jr]=v.w;
        }
        __syncthreads();
        #pragma unroll
        for (int k=0;k<32;k++){
            ulonglong2 A0 = *(const ulonglong2*)(&a_s[k][b0]);
            ulonglong2 A1 = *(const ulonglong2*)(&a_s[k][b0+4]);
            unsigned long long W0, W1;
            PACK2(W0, w_s[k][tvv]);
            PACK2(W1, w_s[k][tvv+64]);
            FFMA2(acc[0][0], A0.x, W0); FFMA2(acc[0][1], A0.y, W0);
            FFMA2(acc[0][2], A1.x, W0); FFMA2(acc[0][3], A1.y, W0);
            FFMA2(acc[1][0], A0.x, W1); FFMA2(acc[1][1], A0.y, W1);
            FFMA2(acc[1][2], A1.x, W1); FFMA2(acc[1][3], A1.y, W1);
        }
        __syncthreads();
    }

    unsigned long long best[8];
    #pragma unroll
    for (int q=0;q<8;q++) best[q] = 0ULL;

    #pragma unroll
    for (int i=0;i<2;i++){
        int v = j0 + tvv + 64*i;
        float bb = bout[v];
        float o[8];
        #pragma unroll
        for (int q=0;q<4;q++) UNPACK2(o[2*q], o[2*q+1], acc[i][q]);
        #pragma unroll
        for (int q=0;q<8;q++){
            float val = o[q] + bb;
            out[((size_t)(b0+q)*T_ + t)*V_ + v] = val;
            unsigned long long p = packv(val, (unsigned)v);
            if (p > best[q]) best[q] = p;
        }
    }
    #pragma unroll
    for (int q=0;q<8;q++) red[b0+q][tvv] = best[q];
    __syncthreads();
    if (tid < B_){
        unsigned long long m = 0ULL;
        #pragma unroll
        for (int i=0;i<64;i++){
            unsigned long long p = red[tid][i];
            if (p > m) m = p;
        }
        atomicMax(&g_argmax[tid], m);
    }
}

// =============================================================================
// init / finalize / log_softmax
// =============================================================================
__global__ void k_init(const float* __restrict__ eh){
    int idx = blockIdx.x*256 + threadIdx.x;           // 0..65535
    int k = idx & (H_-1), b = (idx >> 10) & 31, l = idx >> 15;
    (l ? g_h1T[0] : g_h0T[0])[(size_t)k*B_ + b] = eh[idx];
}

__global__ void k_final(float* __restrict__ dst){
    int idx = blockIdx.x*256 + threadIdx.x;
    int k = idx & (H_-1), b = (idx >> 10) & 31, l = idx >> 15;
    dst[idx] = (l ? g_h1T[0] : g_h0T[0])[(size_t)k*B_ + b];   // parity 0 after 64 steps
}

__global__ __launch_bounds__(256) void k_lsm(float* __restrict__ out){
    float* p = out + (size_t)blockIdx.x * V_;
    __shared__ float red[256];
    float m = -3.4e38f;
    for (int i = threadIdx.x; i < V_; i += 256) m = fmaxf(m, p[i]);
    red[threadIdx.x] = m; __syncthreads();
    for (int s=128; s; s>>=1){
        if (threadIdx.x < s) red[threadIdx.x] = fmaxf(red[threadIdx.x], red[threadIdx.x+s]);
        __syncthreads();
    }
    m = red[0]; __syncthreads();
    float sum = 0.f;
    for (int i = threadIdx.x; i < V_; i += 256) sum += __expf(p[i] - m);
    red[threadIdx.x] = sum; __syncthreads();
    for (int s=128; s; s>>=1){
        if (threadIdx.x < s) red[threadIdx.x] += red[threadIdx.x+s];
        __syncthreads();
    }
    float lse = m + logf(red[0]);
    for (int i = threadIdx.x; i < V_; i += 256) p[i] -= lse;
}

// =============================================================================
extern "C" void kernel_launch(void* const* d_in, const int* in_sizes, int n_in,
                              void* d_out, int out_size) {
    const float* eh   = (const float*)d_in[1];   // encoder_hidden [2,32,1024]
    const float* emb  = (const float*)d_in[2];   // embedding [V,E]
    const float* wih0 = (const float*)d_in[3];
    const float* whh0 = (const float*)d_in[4];
    const float* bih0 = (const float*)d_in[5];
    const float* bhh0 = (const float*)d_in[6];
    const float* wih1 = (const float*)d_in[7];
    const float* whh1 = (const float*)d_in[8];
    const float* bih1 = (const float*)d_in[9];
    const float* bhh1 = (const float*)d_in[10];
    const float* wout = (const float*)d_in[11];
    const float* bout = (const float*)d_in[12];

    float* out  = (float*)d_out;                 // [B,T,V] log-softmax
    float* hfin = out + (size_t)B_*T_*V_;        // [2,B,H]

    k_init<<<256,256>>>(eh);
    for (int t=0; t<T_; t++){
        const int p = t & 1;
        // layer 0: gi = emb[tok] @ wih0^T (split-K), gh = h0_old @ whh0^T
        k_gates<<<NJ_GATES*SPLITK*2,256>>>(wih0, E_, 0, 1, t, whh0, p, emb);
        k_combine<<<H_*B_/256,256>>>(bih0, bhh0, p, 1-p, 0);
        // layer 1: gi = h0_new @ wih1^T, gh = h1_old @ whh1^T
        k_gates<<<NJ_GATES*SPLITK*2,256>>>(wih1, H_, 1-p, 0, t, whh1, 2+p, emb);
        k_combine<<<H_*B_/256,256>>>(bih1, bhh1, 2+p, 3-p, 1);  // also resets argmax
        // logits + fused argmax from h1_new
        k_logits<<<V_/128,256>>>(wout, bout, 3-p, out, t);
    }
    k_final<<<256,256>>>(hfin);
    k_lsm<<<B_*T_,256>>>(out);
}

// round 10
// speedup vs baseline: 1.0817x; 1.0817x over previous
#include <cuda_runtime.h>

#define B_   32
#define T_   64
#define E_   512
#define H_   1024
#define V_   32000
#define G3_  3072
#define SOS_ 1
#define SPLITK 6
#define NJ_GATES  24

// ---------------- persistent device state ----------------
__device__ float g_h0T[2][H_*B_];            // layer-0 hidden, transposed [k][b], ping-pong
__device__ float g_h1T[2][H_*B_];            // layer-1 hidden
__device__ float g_giP[SPLITK][G3_*B_];      // split-K partials x@W_ih^T, layout [j][b]
__device__ float g_ghP[SPLITK][G3_*B_];      // split-K partials h@W_hh^T
__device__ unsigned long long g_argmax[B_];  // packed (orderable_val<<32 | ~index)

__device__ __forceinline__ float* hbuf(int code){
    switch(code){
        case 0:  return g_h0T[0];
        case 1:  return g_h0T[1];
        case 2:  return g_h1T[0];
        default: return g_h1T[1];
    }
}

// packed f32x2 FMA — full-rate fp32 on sm_103a
#define PACK2(dst, f)      asm("mov.b64 %0, {%1, %1};" : "=l"(dst) : "f"(f))
#define FFMA2(acc, a, w)   asm("fma.rn.f32x2 %0, %1, %2, %0;" : "+l"(acc) : "l"(a), "l"(w))
#define UNPACK2(lo, hi, v) asm("mov.b64 {%0, %1}, %2;" : "=f"(lo), "=f"(hi) : "l"(v))

__device__ __forceinline__ unsigned long long packv(float f, unsigned v){
    unsigned u = __float_as_uint(f);
    u = (u & 0x80000000u) ? ~u : (u | 0x80000000u);   // monotonic order-preserving map
    return ((unsigned long long)u << 32) | (unsigned long long)(0xFFFFFFFFu - v);
}

// =============================================================================
// Gates GEMM: out[j][b] = sum_k W[j,k] * a[k][b].  One grid covers both gi and
// gh with split-K=6.  Tile 32b x 128j, 256 thr, register double-buffered.
// =============================================================================
__global__ __launch_bounds__(256,2) void k_gates(
    const float* __restrict__ Wi, int Ki, int code_ai, int gather, int t,
    const float* __restrict__ Wh, int code_ah,
    const float* __restrict__ emb)
{
    __shared__ float w_s[32][129];
    __shared__ float a_s[32][32];
    __shared__ int   tok_s[B_];

    const int bid   = blockIdx.x;
    const int is_gh = (bid >= NJ_GATES*SPLITK);
    const int rem   = is_gh ? bid - NJ_GATES*SPLITK : bid;
    const int s     = rem / NJ_GATES;
    const int j0    = (rem % NJ_GATES) * 128;

    const float* W  = is_gh ? Wh : Wi;
    const int    K  = is_gh ? H_ : Ki;
    float*       out = is_gh ? g_ghP[s] : g_giP[s];
    const float* aT  = hbuf(is_gh ? code_ah : code_ai);
    const bool do_gather = (gather && !is_gh);

    const int TK  = K >> 5;
    const int kt0 = (TK * s) / SPLITK;
    const int kt1 = (TK * (s+1)) / SPLITK;

    const int tid = threadIdx.x;
    const int tvv = tid & 63, b0 = (tid >> 6) * 8;
    const int jr  = tid >> 1, half = tid & 1;

    if (do_gather){
        if (tid < B_){
            int tk = SOS_;
            if (t > 0) tk = (int)(0xFFFFFFFFu - (unsigned)(g_argmax[tid] & 0xFFFFFFFFull));
            tok_s[tid] = tk;
        }
        __syncthreads();
    }

    unsigned long long acc[2][4];
    #pragma unroll
    for (int i=0;i<2;i++){ acc[i][0]=0; acc[i][1]=0; acc[i][2]=0; acc[i][3]=0; }

    const float* wbase = W + (size_t)(j0 + jr)*K + half*16;
    const int gb = tid & 31, ge0 = (tid >> 5) * 4;

    float4 aP, wP[4];
    auto ldA = [&](int kt){
        const int kb = kt*32;
        if (do_gather) aP = *(const float4*)(emb + (size_t)tok_s[gb]*E_ + kb + ge0);
        else           aP = *(const float4*)(aT + (size_t)kb*B_ + tid*4);
    };
    auto ldW = [&](int kt){
        const float* p = wbase + kt*32;
        #pragma unroll
        for (int c=0;c<4;c++) wP[c] = *(const float4*)(p + 4*c);
    };

    ldA(kt0); ldW(kt0);
    for (int kt = kt0; kt < kt1; kt++){
        // ---- stage prefetched regs into smem ----
        if (do_gather){
            a_s[ge0][gb]=aP.x; a_s[ge0+1][gb]=aP.y; a_s[ge0+2][gb]=aP.z; a_s[ge0+3][gb]=aP.w;
        } else {
            *(float4*)((float*)a_s + tid*4) = aP;
        }
        #pragma unroll
        for (int c=0;c<4;c++){
            int kk = half*16 + 4*c;
            w_s[kk][jr]=wP[c].x; w_s[kk+1][jr]=wP[c].y; w_s[kk+2][jr]=wP[c].z; w_s[kk+3][jr]=wP[c].w;
        }
        __syncthreads();
        // ---- issue next tile's global loads (overlaps with FFMA below) ----
        if (kt+1 < kt1){ ldA(kt+1); ldW(kt+1); }
        #pragma unroll
        for (int k=0;k<32;k++){
            ulonglong2 A0 = *(const ulonglong2*)(&a_s[k][b0]);
            ulonglong2 A1 = *(const ulonglong2*)(&a_s[k][b0+4]);
            unsigned long long W0, W1;
            PACK2(W0, w_s[k][tvv]);
            PACK2(W1, w_s[k][tvv+64]);
            FFMA2(acc[0][0], A0.x, W0); FFMA2(acc[0][1], A0.y, W0);
            FFMA2(acc[0][2], A1.x, W0); FFMA2(acc[0][3], A1.y, W0);
            FFMA2(acc[1][0], A0.x, W1); FFMA2(acc[1][1], A0.y, W1);
            FFMA2(acc[1][2], A1.x, W1); FFMA2(acc[1][3], A1.y, W1);
        }
        __syncthreads();
    }
    #pragma unroll
    for (int i=0;i<2;i++){
        int j = j0 + tvv + 64*i;
        float o[8];
        #pragma unroll
        for (int q=0;q<4;q++) UNPACK2(o[2*q], o[2*q+1], acc[i][q]);
        *(float4*)(out + (size_t)j*B_ + b0    ) = make_float4(o[0],o[1],o[2],o[3]);
        *(float4*)(out + (size_t)j*B_ + b0 + 4) = make_float4(o[4],o[5],o[6],o[7]);
    }
}

// =============================================================================
// GRU combine: h_new = (1-z)*n + z*h   (sums split-K partials)
// =============================================================================
__global__ __launch_bounds__(256) void k_combine(
    const float* __restrict__ bih, const float* __restrict__ bhh,
    int code_old, int code_new, int reset)
{
    int idx = blockIdx.x*256 + threadIdx.x;   // 0..32767
    int b = idx & 31, k = idx >> 5;
    float gr=0.f, gz=0.f, gn=0.f, hr=0.f, hz=0.f, hn=0.f;
    #pragma unroll
    for (int s=0;s<SPLITK;s++){
        gr += g_giP[s][(size_t)k*B_ + b];
        gz += g_giP[s][(size_t)(H_  +k)*B_ + b];
        gn += g_giP[s][(size_t)(2*H_+k)*B_ + b];
        hr += g_ghP[s][(size_t)k*B_ + b];
        hz += g_ghP[s][(size_t)(H_  +k)*B_ + b];
        hn += g_ghP[s][(size_t)(2*H_+k)*B_ + b];
    }
    float r = 1.f/(1.f + expf(-(gr + bih[k]     + hr + bhh[k])));
    float z = 1.f/(1.f + expf(-(gz + bih[H_+k]  + hz + bhh[H_+k])));
    float n = tanhf(gn + bih[2*H_+k] + r*(hn + bhh[2*H_+k]));
    float h = hbuf(code_old)[(size_t)k*B_ + b];
    hbuf(code_new)[(size_t)k*B_ + b] = (1.f - z)*n + z*h;
    if (reset && idx < B_) g_argmax[idx] = 0ULL;
}

// =============================================================================
// Logits GEMM + bias + fused per-batch argmax.  250 blocks x 256 thr,
// register double-buffered (hides the 131MB/step w_out DRAM stream).
// =============================================================================
__global__ __launch_bounds__(256,2) void k_logits(
    const float* __restrict__ W, const float* __restrict__ bout,
    int code_h, float* __restrict__ out, int t)
{
    __shared__ float w_s[32][129];
    __shared__ float a_s[32][32];
    __shared__ unsigned long long red[B_][65];

    const float* aT = hbuf(code_h);
    const int j0  = blockIdx.x * 128;
    const int tid = threadIdx.x;
    const int tvv = tid & 63, b0 = (tid >> 6) * 8;
    const int jr  = tid >> 1, half = tid & 1;

    unsigned long long acc[2][4];
    #pragma unroll
    for (int i=0;i<2;i++){ acc[i][0]=0; acc[i][1]=0; acc[i][2]=0; acc[i][3]=0; }

    const float* wbase = W + (size_t)(j0 + jr)*H_ + half*16;

    float4 aP, wP[4];
    auto ldA = [&](int kt){
        aP = *(const float4*)(aT + (size_t)(kt*32)*B_ + tid*4);
    };
    auto ldW = [&](int kt){
        const float* p = wbase + kt*32;
        #pragma unroll
        for (int c=0;c<4;c++) wP[c] = *(const float4*)(p + 4*c);
    };

    ldA(0); ldW(0);
    for (int kt=0; kt<H_/32; kt++){
        *(float4*)((float*)a_s + tid*4) = aP;
        #pragma unroll
        for (int c=0;c<4;c++){
            int kk = half*16 + 4*c;
            w_s[kk][jr]=wP[c].x; w_s[kk+1][jr]=wP[c].y; w_s[kk+2][jr]=wP[c].z; w_s[kk+3][jr]=wP[c].w;
        }
        __syncthreads();
        if (kt+1 < H_/32){ ldA(kt+1); ldW(kt+1); }
        #pragma unroll
        for (int k=0;k<32;k++){
            ulonglong2 A0 = *(const ulonglong2*)(&a_s[k][b0]);
            ulonglong2 A1 = *(const ulonglong2*)(&a_s[k][b0+4]);
            unsigned long long W0, W1;
            PACK2(W0, w_s[k][tvv]);
            PACK2(W1, w_s[k][tvv+64]);
            FFMA2(acc[0][0], A0.x, W0); FFMA2(acc[0][1], A0.y, W0);
            FFMA2(acc[0][2], A1.x, W0); FFMA2(acc[0][3], A1.y, W0);
            FFMA2(acc[1][0], A0.x, W1); FFMA2(acc[1][1], A0.y, W1);
            FFMA2(acc[1][2], A1.x, W1); FFMA2(acc[1][3], A1.y, W1);
        }
        __syncthreads();
    }

    unsigned long long best[8];
    #pragma unroll
    for (int q=0;q<8;q++) best[q] = 0ULL;

    #pragma unroll
    for (int i=0;i<2;i++){
        int v = j0 + tvv + 64*i;
        float bb = bout[v];
        float o[8];
        #pragma unroll
        for (int q=0;q<4;q++) UNPACK2(o[2*q], o[2*q+1], acc[i][q]);
        #pragma unroll
        for (int q=0;q<8;q++){
            float val = o[q] + bb;
            out[((size_t)(b0+q)*T_ + t)*V_ + v] = val;
            unsigned long long p = packv(val, (unsigned)v);
            if (p > best[q]) best[q] = p;
        }
    }
    #pragma unroll
    for (int q=0;q<8;q++) red[b0+q][tvv] = best[q];
    __syncthreads();
    if (tid < B_){
        unsigned long long m = 0ULL;
        #pragma unroll
        for (int i=0;i<64;i++){
            unsigned long long p = red[tid][i];
            if (p > m) m = p;
        }
        atomicMax(&g_argmax[tid], m);
    }
}

// =============================================================================
// init / finalize / log_softmax
// =============================================================================
__global__ void k_init(const float* __restrict__ eh){
    int idx = blockIdx.x*256 + threadIdx.x;           // 0..65535
    int k = idx & (H_-1), b = (idx >> 10) & 31, l = idx >> 15;
    (l ? g_h1T[0] : g_h0T[0])[(size_t)k*B_ + b] = eh[idx];
}

__global__ void k_final(float* __restrict__ dst){
    int idx = blockIdx.x*256 + threadIdx.x;
    int k = idx & (H_-1), b = (idx >> 10) & 31, l = idx >> 15;
    dst[idx] = (l ? g_h1T[0] : g_h0T[0])[(size_t)k*B_ + b];   // parity 0 after 64 steps
}

__global__ __launch_bounds__(256) void k_lsm(float* __restrict__ out){
    float* p = out + (size_t)blockIdx.x * V_;
    __shared__ float red[256];
    float m = -3.4e38f;
    for (int i = threadIdx.x; i < V_; i += 256) m = fmaxf(m, p[i]);
    red[threadIdx.x] = m; __syncthreads();
    for (int s=128; s; s>>=1){
        if (threadIdx.x < s) red[threadIdx.x] = fmaxf(red[threadIdx.x], red[threadIdx.x+s]);
        __syncthreads();
    }
    m = red[0]; __syncthreads();
    float sum = 0.f;
    for (int i = threadIdx.x; i < V_; i += 256) sum += __expf(p[i] - m);
    red[threadIdx.x] = sum; __syncthreads();
    for (int s=128; s; s>>=1){
        if (threadIdx.x < s) red[threadIdx.x] += red[threadIdx.x+s];
        __syncthreads();
    }
    float lse = m + logf(red[0]);
    for (int i = threadIdx.x; i < V_; i += 256) p[i] -= lse;
}

// =============================================================================
extern "C" void kernel_launch(void* const* d_in, const int* in_sizes, int n_in,
                              void* d_out, int out_size) {
    const float* eh   = (const float*)d_in[1];   // encoder_hidden [2,32,1024]
    const float* emb  = (const float*)d_in[2];   // embedding [V,E]
    const float* wih0 = (const float*)d_in[3];
    const float* whh0 = (const float*)d_in[4];
    const float* bih0 = (const float*)d_in[5];
    const float* bhh0 = (const float*)d_in[6];
    const float* wih1 = (const float*)d_in[7];
    const float* whh1 = (const float*)d_in[8];
    const float* bih1 = (const float*)d_in[9];
    const float* bhh1 = (const float*)d_in[10];
    const float* wout = (const float*)d_in[11];
    const float* bout = (const float*)d_in[12];

    float* out  = (float*)d_out;                 // [B,T,V] log-softmax
    float* hfin = out + (size_t)B_*T_*V_;        // [2,B,H]

    k_init<<<256,256>>>(eh);
    for (int t=0; t<T_; t++){
        const int p = t & 1;
        // layer 0: gi = emb[tok] @ wih0^T (split-K), gh = h0_old @ whh0^T
        k_gates<<<NJ_GATES*SPLITK*2,256>>>(wih0, E_, 0, 1, t, whh0, p, emb);
        k_combine<<<H_*B_/256,256>>>(bih0, bhh0, p, 1-p, 0);
        // layer 1: gi = h0_new @ wih1^T, gh = h1_old @ whh1^T
        k_gates<<<NJ_GATES*SPLITK*2,256>>>(wih1, H_, 1-p, 0, t, whh1, 2+p, emb);
        k_combine<<<H_*B_/256,256>>>(bih1, bhh1, 2+p, 3-p, 1);  // also resets argmax
        // logits + fused argmax from h1_new
        k_logits<<<V_/128,256>>>(wout, bout, 3-p, out, t);
    }
    k_final<<<256,256>>>(hfin);
    k_lsm<<<B_*T_,256>>>(out);
}

// round 11
// speedup vs baseline: 1.1647x; 1.0767x over previous
#include <cuda_runtime.h>
#include <cstdint>

#define B_   32
#define T_   64
#define E_   512
#define H_   1024
#define V_   32000
#define G3_  3072
#define SOS_ 1
#define SPLITK 8
#define NJ_GATES  24

// ---------------- persistent device state ----------------
__device__ float g_h0T[2][H_*B_];            // layer-0 hidden, transposed [k][b], ping-pong
__device__ float g_h1T[2][H_*B_];            // layer-1 hidden
__device__ float g_giP[SPLITK][G3_*B_];      // split-K partials x@W_ih^T, layout [j][b]
__device__ float g_ghP[SPLITK][G3_*B_];      // split-K partials h@W_hh^T
__device__ unsigned long long g_argmax[B_];  // packed (orderable_val<<32 | ~index)

// transposed weights [K][N] (filled each replay; amortized over 64 steps)
__device__ float g_wihT0[E_*G3_];
__device__ float g_whhT0[H_*G3_];
__device__ float g_wihT1[H_*G3_];
__device__ float g_whhT1[H_*G3_];
__device__ float g_woutT[H_*V_];

__device__ __forceinline__ float* hbuf(int code){
    switch(code){
        case 0:  return g_h0T[0];
        case 1:  return g_h0T[1];
        case 2:  return g_h1T[0];
        default: return g_h1T[1];
    }
}

// packed f32x2 FMA — full-rate fp32 on sm_103a
#define PACK2(dst, f)      asm("mov.b64 %0, {%1, %1};" : "=l"(dst) : "f"(f))
#define FFMA2(acc, a, w)   asm("fma.rn.f32x2 %0, %1, %2, %0;" : "+l"(acc) : "l"(a), "l"(w))
#define UNPACK2(lo, hi, v) asm("mov.b64 {%0, %1}, %2;" : "=f"(lo), "=f"(hi) : "l"(v))

__device__ __forceinline__ void cpa16(void* s, const void* g){
    asm volatile("cp.async.cg.shared.global [%0], [%1], 16;" ::
        "r"((uint32_t)__cvta_generic_to_shared(s)), "l"(g));
}
#define CP_COMMIT() asm volatile("cp.async.commit_group;" ::: "memory")
#define CP_WAIT1()  asm volatile("cp.async.wait_group 1;" ::: "memory")
#define CP_WAIT0()  asm volatile("cp.async.wait_group 0;" ::: "memory")

__device__ __forceinline__ unsigned long long packv(float f, unsigned v){
    unsigned u = __float_as_uint(f);
    u = (u & 0x80000000u) ? ~u : (u | 0x80000000u);   // monotonic order-preserving map
    return ((unsigned long long)u << 32) | (unsigned long long)(0xFFFFFFFFu - v);
}

#define WS_STRIDE 136   // floats per k-row of w_s: 136*4B = 544B (16B-aligned), banks (8k+j)%32

// =============================================================================
// Gates GEMM: out[j][b] = sum_k WT[k][j] * a[k][b].  One grid covers gi & gh,
// split-K=8.  Tile 32k x 128j x 32b, 256 thr, cp.async 2-stage pipeline.
// =============================================================================
__global__ __launch_bounds__(256,3) void k_gates(int layer, int code_ai, int gather, int t,
                                                 int code_ah, const float* __restrict__ emb)
{
    __shared__ float w_s[2][32*WS_STRIDE];
    __shared__ float a_s[2][32*32];
    __shared__ int   tok_s[B_];

    const int bid   = blockIdx.x;
    const int is_gh = (bid >= NJ_GATES*SPLITK);
    const int rem   = is_gh ? bid - NJ_GATES*SPLITK : bid;
    const int s     = rem / NJ_GATES;
    const int j0    = (rem % NJ_GATES) * 128;

    const float* WT;
    int K;
    if (is_gh){ WT = layer ? g_whhT1 : g_whhT0; K = H_; }
    else      { WT = layer ? g_wihT1 : g_wihT0; K = layer ? H_ : E_; }
    float*       out = is_gh ? g_ghP[s] : g_giP[s];
    const float* aT  = hbuf(is_gh ? code_ah : code_ai);
    const bool do_gather = (gather && !is_gh);

    const int TK  = K >> 5;
    const int kt0 = (TK * s) / SPLITK;
    const int kt1 = (TK * (s+1)) / SPLITK;
    const int NT  = kt1 - kt0;

    const int tid = threadIdx.x;
    const int tvv = tid & 63, b0 = (tid >> 6) * 8;
    const int sk  = tid >> 3;            // k-row this thread copies (0..31)
    const int sc  = (tid & 7) * 16;      // starting float col of its 64B W chunk
    const int ac4 = (tid & 7) * 4;       // A chunk col (floats)
    const int gb  = tid & 31, ge0 = (tid >> 5) * 4;   // gather mapping

    if (do_gather){
        if (tid < B_){
            int tk = SOS_;
            if (t > 0) tk = (int)(0xFFFFFFFFu - (unsigned)(g_argmax[tid] & 0xFFFFFFFFull));
            tok_s[tid] = tk;
        }
        __syncthreads();
    }

    // ---- staging helpers ----
    auto stage_w = [&](int kt, int st){
        const float* src = WT + (size_t)(kt*32 + sk)*G3_ + j0 + sc;
        float* dst = &w_s[st][sk*WS_STRIDE + sc];
        #pragma unroll
        for (int c=0;c<4;c++) cpa16(dst + 4*c, src + 4*c);
    };
    auto stage_a_async = [&](int kt, int st){
        cpa16(&a_s[st][sk*32 + ac4], aT + (size_t)(kt*32 + sk)*B_ + ac4);
    };
    auto stage_a_gather = [&](int kt, int st){
        const float4 v = *(const float4*)(emb + (size_t)tok_s[gb]*E_ + kt*32 + ge0);
        a_s[st][(ge0  )*32 + gb] = v.x;
        a_s[st][(ge0+1)*32 + gb] = v.y;
        a_s[st][(ge0+2)*32 + gb] = v.z;
        a_s[st][(ge0+3)*32 + gb] = v.w;
    };

    // ---- prologue: stage up to 2 tiles ----
    stage_w(kt0, 0);
    if (!do_gather) stage_a_async(kt0, 0); else stage_a_gather(kt0, 0);
    CP_COMMIT();
    if (NT > 1){
        stage_w(kt0+1, 1);
        if (!do_gather) stage_a_async(kt0+1, 1); else stage_a_gather(kt0+1, 1);
        CP_COMMIT();
    }

    unsigned long long acc[2][4];
    #pragma unroll
    for (int i=0;i<2;i++){ acc[i][0]=0; acc[i][1]=0; acc[i][2]=0; acc[i][3]=0; }

    for (int kt = 0; kt < NT; kt++){
        const int st = kt & 1;
        if (kt < NT-1) CP_WAIT1(); else CP_WAIT0();
        __syncthreads();
        #pragma unroll
        for (int k=0;k<32;k++){
            ulonglong2 A0 = *(const ulonglong2*)(&a_s[st][k*32 + b0]);
            ulonglong2 A1 = *(const ulonglong2*)(&a_s[st][k*32 + b0 + 4]);
            unsigned long long W0, W1;
            PACK2(W0, w_s[st][k*WS_STRIDE + tvv]);
            PACK2(W1, w_s[st][k*WS_STRIDE + tvv + 64]);
            FFMA2(acc[0][0], A0.x, W0); FFMA2(acc[0][1], A0.y, W0);
            FFMA2(acc[0][2], A1.x, W0); FFMA2(acc[0][3], A1.y, W0);
            FFMA2(acc[1][0], A0.x, W1); FFMA2(acc[1][1], A0.y, W1);
            FFMA2(acc[1][2], A1.x, W1); FFMA2(acc[1][3], A1.y, W1);
        }
        __syncthreads();
        if (kt + 2 < NT){
            stage_w(kt0+kt+2, st);
            if (!do_gather) stage_a_async(kt0+kt+2, st); else stage_a_gather(kt0+kt+2, st);
            CP_COMMIT();
        }
    }

    #pragma unroll
    for (int i=0;i<2;i++){
        int j = j0 + tvv + 64*i;
        float o[8];
        #pragma unroll
        for (int q=0;q<4;q++) UNPACK2(o[2*q], o[2*q+1], acc[i][q]);
        *(float4*)(out + (size_t)j*B_ + b0    ) = make_float4(o[0],o[1],o[2],o[3]);
        *(float4*)(out + (size_t)j*B_ + b0 + 4) = make_float4(o[4],o[5],o[6],o[7]);
    }
}

// =============================================================================
// GRU combine: h_new = (1-z)*n + z*h   (sums split-K partials)
// =============================================================================
__global__ __launch_bounds__(256) void k_combine(
    const float* __restrict__ bih, const float* __restrict__ bhh,
    int code_old, int code_new, int reset)
{
    int idx = blockIdx.x*256 + threadIdx.x;   // 0..32767
    int b = idx & 31, k = idx >> 5;
    float gr=0.f, gz=0.f, gn=0.f, hr=0.f, hz=0.f, hn=0.f;
    #pragma unroll
    for (int s=0;s<SPLITK;s++){
        gr += g_giP[s][(size_t)k*B_ + b];
        gz += g_giP[s][(size_t)(H_  +k)*B_ + b];
        gn += g_giP[s][(size_t)(2*H_+k)*B_ + b];
        hr += g_ghP[s][(size_t)k*B_ + b];
        hz += g_ghP[s][(size_t)(H_  +k)*B_ + b];
        hn += g_ghP[s][(size_t)(2*H_+k)*B_ + b];
    }
    float r = 1.f/(1.f + expf(-(gr + bih[k]     + hr + bhh[k])));
    float z = 1.f/(1.f + expf(-(gz + bih[H_+k]  + hz + bhh[H_+k])));
    float n = tanhf(gn + bih[2*H_+k] + r*(hn + bhh[2*H_+k]));
    float h = hbuf(code_old)[(size_t)k*B_ + b];
    hbuf(code_new)[(size_t)k*B_ + b] = (1.f - z)*n + z*h;
    if (reset && idx < B_) g_argmax[idx] = 0ULL;
}

// =============================================================================
// Logits GEMM + bias + fused per-batch argmax.  250 blocks x 256 thr,
// cp.async 2-stage pipeline on pre-transposed w_out.
// =============================================================================
__global__ __launch_bounds__(256,3) void k_logits(
    const float* __restrict__ bout, int code_h, float* __restrict__ out, int t)
{
    __shared__ float w_s[2][32*WS_STRIDE];
    __shared__ float a_s[2][32*32];
    __shared__ unsigned long long red[B_][2];

    const float* aT = hbuf(code_h);
    const float* WT = g_woutT;
    const int j0  = blockIdx.x * 128;
    const int tid = threadIdx.x;
    const int tvv = tid & 63, b0 = (tid >> 6) * 8;
    const int sk  = tid >> 3;
    const int sc  = (tid & 7) * 16;
    const int ac4 = (tid & 7) * 4;
    const int NT  = H_/32;

    auto stage_w = [&](int kt, int st){
        const float* src = WT + (size_t)(kt*32 + sk)*V_ + j0 + sc;
        float* dst = &w_s[st][sk*WS_STRIDE + sc];
        #pragma unroll
        for (int c=0;c<4;c++) cpa16(dst + 4*c, src + 4*c);
    };
    auto stage_a = [&](int kt, int st){
        cpa16(&a_s[st][sk*32 + ac4], aT + (size_t)(kt*32 + sk)*B_ + ac4);
    };

    stage_w(0,0); stage_a(0,0); CP_COMMIT();
    stage_w(1,1); stage_a(1,1); CP_COMMIT();

    unsigned long long acc[2][4];
    #pragma unroll
    for (int i=0;i<2;i++){ acc[i][0]=0; acc[i][1]=0; acc[i][2]=0; acc[i][3]=0; }

    for (int kt=0; kt<NT; kt++){
        const int st = kt & 1;
        if (kt < NT-1) CP_WAIT1(); else CP_WAIT0();
        __syncthreads();
        #pragma unroll
        for (int k=0;k<32;k++){
            ulonglong2 A0 = *(const ulonglong2*)(&a_s[st][k*32 + b0]);
            ulonglong2 A1 = *(const ulonglong2*)(&a_s[st][k*32 + b0 + 4]);
            unsigned long long W0, W1;
            PACK2(W0, w_s[st][k*WS_STRIDE + tvv]);
            PACK2(W1, w_s[st][k*WS_STRIDE + tvv + 64]);
            FFMA2(acc[0][0], A0.x, W0); FFMA2(acc[0][1], A0.y, W0);
            FFMA2(acc[0][2], A1.x, W0); FFMA2(acc[0][3], A1.y, W0);
            FFMA2(acc[1][0], A0.x, W1); FFMA2(acc[1][1], A0.y, W1);
            FFMA2(acc[1][2], A1.x, W1); FFMA2(acc[1][3], A1.y, W1);
        }
        __syncthreads();
        if (kt + 2 < NT){ stage_w(kt+2, st); stage_a(kt+2, st); CP_COMMIT(); }
    }

    // ---- epilogue: +bias, store logits, warp-shuffle argmax ----
    unsigned long long best[8];
    #pragma unroll
    for (int q=0;q<8;q++) best[q] = 0ULL;

    #pragma unroll
    for (int i=0;i<2;i++){
        int v = j0 + tvv + 64*i;
        float bb = bout[v];
        float o[8];
        #pragma unroll
        for (int q=0;q<4;q++) UNPACK2(o[2*q], o[2*q+1], acc[i][q]);
        #pragma unroll
        for (int q=0;q<8;q++){
            float val = o[q] + bb;
            out[((size_t)(b0+q)*T_ + t)*V_ + v] = val;
            unsigned long long p = packv(val, (unsigned)v);
            if (p > best[q]) best[q] = p;
        }
    }
    // reduce across the 32 lanes of this warp (all share the same b0)
    #pragma unroll
    for (int q=0;q<8;q++){
        #pragma unroll
        for (int off=16; off; off>>=1){
            unsigned long long o = __shfl_xor_sync(0xFFFFFFFFu, best[q], off);
            if (o > best[q]) best[q] = o;
        }
    }
    const int wid = tid >> 5, lane = tid & 31;
    if (lane == 0){
        #pragma unroll
        for (int q=0;q<8;q++) red[b0+q][wid & 1] = best[q];
    }
    __syncthreads();
    if (tid < B_){
        unsigned long long m = red[tid][0];
        if (red[tid][1] > m) m = red[tid][1];
        atomicMax(&g_argmax[tid], m);
    }
}

// =============================================================================
// weight transpose (runs once per replay): in [R][C] -> outT [C][R]
// =============================================================================
__global__ void k_transpose(const float* __restrict__ in, int R, int C, int which){
    float* out = (which==0) ? g_wihT0 :
                 (which==1) ? g_whhT0 :
                 (which==2) ? g_wihT1 :
                 (which==3) ? g_whhT1 : g_woutT;
    __shared__ float tile[32][33];
    const int c0 = blockIdx.x*32, r0 = blockIdx.y*32;
    const int x = threadIdx.x, y = threadIdx.y;
    #pragma unroll
    for (int dy=0; dy<32; dy+=8)
        tile[y+dy][x] = in[(size_t)(r0+y+dy)*C + c0 + x];
    __syncthreads();
    #pragma unroll
    for (int dy=0; dy<32; dy+=8)
        out[(size_t)(c0+y+dy)*R + r0 + x] = tile[x][y+dy];
}

// =============================================================================
// init / finalize / log_softmax
// =============================================================================
__global__ void k_init(const float* __restrict__ eh){
    int idx = blockIdx.x*256 + threadIdx.x;           // 0..65535
    int k = idx & (H_-1), b = (idx >> 10) & 31, l = idx >> 15;
    (l ? g_h1T[0] : g_h0T[0])[(size_t)k*B_ + b] = eh[idx];
}

__global__ void k_final(float* __restrict__ dst){
    int idx = blockIdx.x*256 + threadIdx.x;
    int k = idx & (H_-1), b = (idx >> 10) & 31, l = idx >> 15;
    dst[idx] = (l ? g_h1T[0] : g_h0T[0])[(size_t)k*B_ + b];   // parity 0 after 64 steps
}

__global__ __launch_bounds__(256) void k_lsm(float* __restrict__ out){
    float* p = out + (size_t)blockIdx.x * V_;
    __shared__ float red[256];
    float m = -3.4e38f;
    for (int i = threadIdx.x; i < V_; i += 256) m = fmaxf(m, p[i]);
    red[threadIdx.x] = m; __syncthreads();
    for (int s=128; s; s>>=1){
        if (threadIdx.x < s) red[threadIdx.x] = fmaxf(red[threadIdx.x], red[threadIdx.x+s]);
        __syncthreads();
    }
    m = red[0]; __syncthreads();
    float sum = 0.f;
    for (int i = threadIdx.x; i < V_; i += 256) sum += __expf(p[i] - m);
    red[threadIdx.x] = sum; __syncthreads();
    for (int s=128; s; s>>=1){
        if (threadIdx.x < s) red[threadIdx.x] += red[threadIdx.x+s];
        __syncthreads();
    }
    float lse = m + logf(red[0]);
    for (int i = threadIdx.x; i < V_; i += 256) p[i] -= lse;
}

// =============================================================================
extern "C" void kernel_launch(void* const* d_in, const int* in_sizes, int n_in,
                              void* d_out, int out_size) {
    const float* eh   = (const float*)d_in[1];   // encoder_hidden [2,32,1024]
    const float* emb  = (const float*)d_in[2];   // embedding [V,E]
    const float* wih0 = (const float*)d_in[3];
    const float* whh0 = (const float*)d_in[4];
    const float* bih0 = (const float*)d_in[5];
    const float* bhh0 = (const float*)d_in[6];
    const float* wih1 = (const float*)d_in[7];
    const float* whh1 = (const float*)d_in[8];
    const float* bih1 = (const float*)d_in[9];
    const float* bhh1 = (const float*)d_in[10];
    const float* wout = (const float*)d_in[11];
    const float* bout = (const float*)d_in[12];

    float* out  = (float*)d_out;                 // [B,T,V] log-softmax
    float* hfin = out + (size_t)B_*T_*V_;        // [2,B,H]

    // per-replay weight transposes (amortized over 64 steps)
    dim3 tb(32,8);
    k_transpose<<<dim3(E_/32,  G3_/32), tb>>>(wih0, G3_, E_, 0);
    k_transpose<<<dim3(H_/32,  G3_/32), tb>>>(whh0, G3_, H_, 1);
    k_transpose<<<dim3(H_/32,  G3_/32), tb>>>(wih1, G3_, H_, 2);
    k_transpose<<<dim3(H_/32,  G3_/32), tb>>>(whh1, G3_, H_, 3);
    k_transpose<<<dim3(H_/32,  V_/32),  tb>>>(wout, V_,  H_, 4);

    k_init<<<256,256>>>(eh);
    for (int t=0; t<T_; t++){
        const int p = t & 1;
        // layer 0: gi = emb[tok] @ wih0^T (gather), gh = h0_old @ whh0^T
        k_gates<<<NJ_GATES*SPLITK*2,256>>>(0, 0, 1, t, p, emb);
        k_combine<<<H_*B_/256,256>>>(bih0, bhh0, p, 1-p, 0);
        // layer 1: gi = h0_new @ wih1^T, gh = h1_old @ whh1^T
        k_gates<<<NJ_GATES*SPLITK*2,256>>>(1, 1-p, 0, t, 2+p, emb);
        k_combine<<<H_*B_/256,256>>>(bih1, bhh1, 2+p, 3-p, 1);  // also resets argmax
        // logits + fused argmax from h1_new
        k_logits<<<V_/128,256>>>(bout, 3-p, out, t);
    }
    k_final<<<256,256>>>(hfin);
    k_lsm<<<B_*T_,256>>>(out);
}

// round 13
// speedup vs baseline: 1.8571x; 1.5946x over previous
#include <cuda_runtime.h>
#include <cuda_bf16.h>
#include <cstdint>

#define B_   32
#define T_   64
#define E_   512
#define H_   1024
#define V_   32000
#define G3_  3072
#define SOS_ 1
#define SPLITK 8
#define NJ_GATES  24
#define VT_  250      // vocab tiles of 128
#define KT_  64       // K tiles of 16

// ---------------- persistent device state ----------------
__device__ float g_h0T[2][H_*B_];            // layer-0 hidden, transposed [k][b], ping-pong
__device__ float g_h1T[2][H_*B_];            // layer-1 hidden
__device__ float g_giP[SPLITK][G3_*B_];      // split-K partials x@W_ih^T, layout [j][b]
__device__ float g_ghP[SPLITK][G3_*B_];      // split-K partials h@W_hh^T
__device__ unsigned long long g_argmax[B_];  // packed (orderable_val<<32 | ~index)

// transposed gate weights [K][N] (filled each replay)
__device__ float g_wihT0[E_*G3_];
__device__ float g_whhT0[H_*G3_];
__device__ float g_wihT1[H_*G3_];
__device__ float g_whhT1[H_*G3_];

// w_out bf16 hi/lo in per-lane MMA A-fragment layout:
// index ((vt*8 + mtile)*64 + ktile)*32 + lane  -> uint4 (regs a0..a3)
__device__ uint4 g_wfHi[(size_t)VT_*8*KT_*32];
__device__ uint4 g_wfLo[(size_t)VT_*8*KT_*32];
// h1 bf16 hi/lo in B-fragment layout: index (ktile*4 + ntile)*32 + lane -> uint2
__device__ uint2 g_hfHi[KT_*4*32];
__device__ uint2 g_hfLo[KT_*4*32];

__device__ __forceinline__ float* hbuf(int code){
    switch(code){
        case 0:  return g_h0T[0];
        case 1:  return g_h0T[1];
        case 2:  return g_h1T[0];
        default: return g_h1T[1];
    }
}

// packed f32x2 FMA — full-rate fp32 on sm_103a
#define PACK2(dst, f)      asm("mov.b64 %0, {%1, %1};" : "=l"(dst) : "f"(f))
#define FFMA2(acc, a, w)   asm("fma.rn.f32x2 %0, %1, %2, %0;" : "+l"(acc) : "l"(a), "l"(w))
#define UNPACK2(lo, hi, v) asm("mov.b64 {%0, %1}, %2;" : "=f"(lo), "=f"(hi) : "l"(v))

__device__ __forceinline__ void cpa16(void* s, const void* g){
    asm volatile("cp.async.cg.shared.global [%0], [%1], 16;" ::
        "r"((uint32_t)__cvta_generic_to_shared(s)), "l"(g));
}
#define CP_COMMIT() asm volatile("cp.async.commit_group;" ::: "memory")
#define CP_WAIT1()  asm volatile("cp.async.wait_group 1;" ::: "memory")
#define CP_WAIT0()  asm volatile("cp.async.wait_group 0;" ::: "memory")

__device__ __forceinline__ unsigned long long packv(float f, unsigned v){
    unsigned u = __float_as_uint(f);
    u = (u & 0x80000000u) ? ~u : (u | 0x80000000u);   // monotonic order-preserving map
    return ((unsigned long long)u << 32) | (unsigned long long)(0xFFFFFFFFu - v);
}

// baseline-sm_103 HMMA: m16n8k16 bf16 -> f32, accumulate in place
__device__ __forceinline__ void mma16816(float* d, const uint32_t* a, const uint32_t* b){
    asm volatile("mma.sync.aligned.m16n8k16.row.col.f32.bf16.bf16.f32 "
        "{%0,%1,%2,%3}, {%4,%5,%6,%7}, {%8,%9}, {%0,%1,%2,%3};"
        : "+f"(d[0]), "+f"(d[1]), "+f"(d[2]), "+f"(d[3])
        : "r"(a[0]), "r"(a[1]), "r"(a[2]), "r"(a[3]), "r"(b[0]), "r"(b[1]));
}

#define WS_STRIDE 136   // floats per k-row of gates w_s

// =============================================================================
// Gates GEMM (unchanged, passing since R11): out[j][b] = sum_k WT[k][j]*a[k][b]
// =============================================================================
__global__ __launch_bounds__(256,3) void k_gates(int layer, int code_ai, int gather, int t,
                                                 int code_ah, const float* __restrict__ emb)
{
    __shared__ float w_s[2][32*WS_STRIDE];
    __shared__ float a_s[2][32*32];
    __shared__ int   tok_s[B_];

    const int bid   = blockIdx.x;
    const int is_gh = (bid >= NJ_GATES*SPLITK);
    const int rem   = is_gh ? bid - NJ_GATES*SPLITK : bid;
    const int s     = rem / NJ_GATES;
    const int j0    = (rem % NJ_GATES) * 128;

    const float* WT;
    int K;
    if (is_gh){ WT = layer ? g_whhT1 : g_whhT0; K = H_; }
    else      { WT = layer ? g_wihT1 : g_wihT0; K = layer ? H_ : E_; }
    float*       out = is_gh ? g_ghP[s] : g_giP[s];
    const float* aT  = hbuf(is_gh ? code_ah : code_ai);
    const bool do_gather = (gather && !is_gh);

    const int TK  = K >> 5;
    const int kt0 = (TK * s) / SPLITK;
    const int kt1 = (TK * (s+1)) / SPLITK;
    const int NT  = kt1 - kt0;

    const int tid = threadIdx.x;
    const int tvv = tid & 63, b0 = (tid >> 6) * 8;
    const int sk  = tid >> 3;
    const int sc  = (tid & 7) * 16;
    const int ac4 = (tid & 7) * 4;
    const int gb  = tid & 31, ge0 = (tid >> 5) * 4;

    if (do_gather){
        if (tid < B_){
            int tk = SOS_;
            if (t > 0) tk = (int)(0xFFFFFFFFu - (unsigned)(g_argmax[tid] & 0xFFFFFFFFull));
            tok_s[tid] = tk;
        }
        __syncthreads();
    }

    auto stage_w = [&](int kt, int st){
        const float* src = WT + (size_t)(kt*32 + sk)*G3_ + j0 + sc;
        float* dst = &w_s[st][sk*WS_STRIDE + sc];
        #pragma unroll
        for (int c=0;c<4;c++) cpa16(dst + 4*c, src + 4*c);
    };
    auto stage_a_async = [&](int kt, int st){
        cpa16(&a_s[st][sk*32 + ac4], aT + (size_t)(kt*32 + sk)*B_ + ac4);
    };
    auto stage_a_gather = [&](int kt, int st){
        const float4 v = *(const float4*)(emb + (size_t)tok_s[gb]*E_ + kt*32 + ge0);
        a_s[st][(ge0  )*32 + gb] = v.x;
        a_s[st][(ge0+1)*32 + gb] = v.y;
        a_s[st][(ge0+2)*32 + gb] = v.z;
        a_s[st][(ge0+3)*32 + gb] = v.w;
    };

    stage_w(kt0, 0);
    if (!do_gather) stage_a_async(kt0, 0); else stage_a_gather(kt0, 0);
    CP_COMMIT();
    if (NT > 1){
        stage_w(kt0+1, 1);
        if (!do_gather) stage_a_async(kt0+1, 1); else stage_a_gather(kt0+1, 1);
        CP_COMMIT();
    }

    unsigned long long acc[2][4];
    #pragma unroll
    for (int i=0;i<2;i++){ acc[i][0]=0; acc[i][1]=0; acc[i][2]=0; acc[i][3]=0; }

    for (int kt = 0; kt < NT; kt++){
        const int st = kt & 1;
        if (kt < NT-1) CP_WAIT1(); else CP_WAIT0();
        __syncthreads();
        #pragma unroll
        for (int k=0;k<32;k++){
            ulonglong2 A0 = *(const ulonglong2*)(&a_s[st][k*32 + b0]);
            ulonglong2 A1 = *(const ulonglong2*)(&a_s[st][k*32 + b0 + 4]);
            unsigned long long W0, W1;
            PACK2(W0, w_s[st][k*WS_STRIDE + tvv]);
            PACK2(W1, w_s[st][k*WS_STRIDE + tvv + 64]);
            FFMA2(acc[0][0], A0.x, W0); FFMA2(acc[0][1], A0.y, W0);
            FFMA2(acc[0][2], A1.x, W0); FFMA2(acc[0][3], A1.y, W0);
            FFMA2(acc[1][0], A0.x, W1); FFMA2(acc[1][1], A0.y, W1);
            FFMA2(acc[1][2], A1.x, W1); FFMA2(acc[1][3], A1.y, W1);
        }
        __syncthreads();
        if (kt + 2 < NT){
            stage_w(kt0+kt+2, st);
            if (!do_gather) stage_a_async(kt0+kt+2, st); else stage_a_gather(kt0+kt+2, st);
            CP_COMMIT();
        }
    }

    #pragma unroll
    for (int i=0;i<2;i++){
        int j = j0 + tvv + 64*i;
        float o[8];
        #pragma unroll
        for (int q=0;q<4;q++) UNPACK2(o[2*q], o[2*q+1], acc[i][q]);
        *(float4*)(out + (size_t)j*B_ + b0    ) = make_float4(o[0],o[1],o[2],o[3]);
        *(float4*)(out + (size_t)j*B_ + b0 + 4) = make_float4(o[4],o[5],o[6],o[7]);
    }
}

// =============================================================================
// GRU combine; layer-1 variant also writes h bf16 hi/lo B-fragments + resets
// =============================================================================
__global__ __launch_bounds__(256) void k_combine(
    const float* __restrict__ bih, const float* __restrict__ bhh,
    int code_old, int code_new, int reset)
{
    int idx = blockIdx.x*256 + threadIdx.x;   // 0..32767
    int b = idx & 31, k = idx >> 5;
    float gr=0.f, gz=0.f, gn=0.f, hr=0.f, hz=0.f, hn=0.f;
    #pragma unroll
    for (int s=0;s<SPLITK;s++){
        gr += g_giP[s][(size_t)k*B_ + b];
        gz += g_giP[s][(size_t)(H_  +k)*B_ + b];
        gn += g_giP[s][(size_t)(2*H_+k)*B_ + b];
        hr += g_ghP[s][(size_t)k*B_ + b];
        hz += g_ghP[s][(size_t)(H_  +k)*B_ + b];
        hn += g_ghP[s][(size_t)(2*H_+k)*B_ + b];
    }
    float r = 1.f/(1.f + expf(-(gr + bih[k]     + hr + bhh[k])));
    float z = 1.f/(1.f + expf(-(gz + bih[H_+k]  + hz + bhh[H_+k])));
    float n = tanhf(gn + bih[2*H_+k] + r*(hn + bhh[2*H_+k]));
    float h = hbuf(code_old)[(size_t)k*B_ + b];
    float hv = (1.f - z)*n + z*h;
    hbuf(code_new)[(size_t)k*B_ + b] = hv;

    if (reset){
        // B-fragment placement for mma.m16n8k16 (.row.col):
        // b-reg0 = {B[kin=(lane%4)*2][n], B[kin+1][n]}, b-reg1 = same +8
        __nv_bfloat16 hi = __float2bfloat16(hv);
        __nv_bfloat16 lo = __float2bfloat16(hv - __bfloat162float(hi));
        int ktile = k >> 4, kin = k & 15;
        int reg = kin >> 3, c = kin & 7;
        int lane = (b & 7)*4 + (c >> 1);
        int ntile = b >> 3;
        int half = c & 1;
        size_t off = ((size_t)(ktile*4 + ntile)*32 + lane)*4 + reg*2 + half; // ushort units
        ((unsigned short*)g_hfHi)[off] = __bfloat16_as_ushort(hi);
        ((unsigned short*)g_hfLo)[off] = __bfloat16_as_ushort(lo);
        if (idx < B_) g_argmax[idx] = 0ULL;
    }
}

// =============================================================================
// w_out -> bf16 hi/lo per-lane A-fragments (once per replay)
// One thread per (vt, mtile, ktile, lane): produces uint4 hi + uint4 lo.
// =============================================================================
__global__ __launch_bounds__(256) void k_wsplit(const float* __restrict__ w){
    size_t gid = (size_t)blockIdx.x*256 + threadIdx.x;  // 250*8*64*32 = 4,096,000
    int lane  = (int)(gid & 31);
    int ktile = (int)((gid >> 5) & 63);
    int mtile = (int)((gid >> 11) & 7);
    int vt    = (int)(gid >> 14);
    int g  = lane >> 2, c0 = (lane & 3)*2;
    int v0 = vt*128 + mtile*16;
    int k0 = ktile*16;
    uint32_t hi[4], lo[4];
    #pragma unroll
    for (int r=0;r<4;r++){
        int row = v0 + g + (r & 1)*8;
        int col = k0 + c0 + (r >> 1)*8;
        float x0 = w[(size_t)row*H_ + col];
        float x1 = w[(size_t)row*H_ + col + 1];
        __nv_bfloat16 h0 = __float2bfloat16(x0), h1 = __float2bfloat16(x1);
        __nv_bfloat16 l0 = __float2bfloat16(x0 - __bfloat162float(h0));
        __nv_bfloat16 l1 = __float2bfloat16(x1 - __bfloat162float(h1));
        hi[r] = (uint32_t)__bfloat16_as_ushort(h0) | ((uint32_t)__bfloat16_as_ushort(h1) << 16);
        lo[r] = (uint32_t)__bfloat16_as_ushort(l0) | ((uint32_t)__bfloat16_as_ushort(l1) << 16);
    }
    g_wfHi[gid] = make_uint4(hi[0], hi[1], hi[2], hi[3]);
    g_wfLo[gid] = make_uint4(lo[0], lo[1], lo[2], lo[3]);
}

// =============================================================================
// Logits via mma.sync bf16 hi/lo (3 cross terms) + bias + fused argmax.
// 250 blocks x 256 thr (8 warps); warp = 16 vocab rows x 32 batch.
// =============================================================================
__global__ __launch_bounds__(256,3) void k_logits_mma(
    const float* __restrict__ bout, float* __restrict__ out, int t)
{
    __shared__ unsigned long long red[8][32];

    const int tid = threadIdx.x, wid = tid >> 5, lane = tid & 31;
    const int vt  = blockIdx.x;

    float acc[4][4];
    #pragma unroll
    for (int n=0;n<4;n++){ acc[n][0]=0.f; acc[n][1]=0.f; acc[n][2]=0.f; acc[n][3]=0.f; }

    const uint4* __restrict__ aHi = g_wfHi + ((size_t)(vt*8 + wid)*KT_)*32 + lane;
    const uint4* __restrict__ aLo = g_wfLo + ((size_t)(vt*8 + wid)*KT_)*32 + lane;

    uint4 ah = aHi[0], al = aLo[0];
    for (int kt = 0; kt < KT_; kt++){
        uint4 ah_n, al_n;
        if (kt < KT_-1){ ah_n = aHi[(kt+1)*32]; al_n = aLo[(kt+1)*32]; }
        uint2 bh[4], bl[4];
        #pragma unroll
        for (int nt=0; nt<4; nt++){
            bh[nt] = g_hfHi[(kt*4 + nt)*32 + lane];
            bl[nt] = g_hfLo[(kt*4 + nt)*32 + lane];
        }
        #pragma unroll
        for (int nt=0; nt<4; nt++){
            mma16816(acc[nt], (const uint32_t*)&ah, (const uint32_t*)&bh[nt]);
            mma16816(acc[nt], (const uint32_t*)&ah, (const uint32_t*)&bl[nt]);
            mma16816(acc[nt], (const uint32_t*)&al, (const uint32_t*)&bh[nt]);
        }
        ah = ah_n; al = al_n;
    }

    // epilogue: D[row=g(+8)][col=nt*8 + (lane%4)*2 (+1)]
    const int g  = lane >> 2, c0 = (lane & 3)*2;
    const int v0 = vt*128 + wid*16 + g;
    const float bias0 = bout[v0], bias1 = bout[v0 + 8];

    unsigned long long colmax[8];
    #pragma unroll
    for (int nt=0; nt<4; nt++){
        const int b = nt*8 + c0;
        float v00 = acc[nt][0] + bias0;   // (v0,   b)
        float v01 = acc[nt][1] + bias0;   // (v0,   b+1)
        float v10 = acc[nt][2] + bias1;   // (v0+8, b)
        float v11 = acc[nt][3] + bias1;   // (v0+8, b+1)
        out[((size_t)b    *T_ + t)*V_ + v0    ] = v00;
        out[((size_t)(b+1)*T_ + t)*V_ + v0    ] = v01;
        out[((size_t)b    *T_ + t)*V_ + v0 + 8] = v10;
        out[((size_t)(b+1)*T_ + t)*V_ + v0 + 8] = v11;
        unsigned long long p0 = packv(v00, (unsigned)v0);
        unsigned long long q0 = packv(v10, (unsigned)(v0+8));
        unsigned long long p1 = packv(v01, (unsigned)v0);
        unsigned long long q1 = packv(v11, (unsigned)(v0+8));
        colmax[nt*2]   = p0 > q0 ? p0 : q0;
        colmax[nt*2+1] = p1 > q1 ? p1 : q1;
    }
    // reduce over the 8 row-groups (lanes differing in bits 2..4)
    #pragma unroll
    for (int q=0;q<8;q++){
        #pragma unroll
        for (int off=4; off<32; off<<=1){
            unsigned long long o = __shfl_xor_sync(0xFFFFFFFFu, colmax[q], off);
            if (o > colmax[q]) colmax[q] = o;
        }
    }
    if (lane < 4){
        #pragma unroll
        for (int nt=0; nt<4; nt++){
            red[wid][nt*8 + lane*2    ] = colmax[nt*2];
            red[wid][nt*8 + lane*2 + 1] = colmax[nt*2+1];
        }
    }
    __syncthreads();
    if (tid < B_){
        unsigned long long m = red[0][tid];
        #pragma unroll
        for (int w=1; w<8; w++) if (red[w][tid] > m) m = red[w][tid];
        atomicMax(&g_argmax[tid], m);
    }
}

// =============================================================================
// weight transpose (gate weights, once per replay): in [R][C] -> outT [C][R]
// =============================================================================
__global__ void k_transpose(const float* __restrict__ in, int R, int C, int which){
    float* out = (which==0) ? g_wihT0 :
                 (which==1) ? g_whhT0 :
                 (which==2) ? g_wihT1 : g_whhT1;
    __shared__ float tile[32][33];
    const int c0 = blockIdx.x*32, r0 = blockIdx.y*32;
    const int x = threadIdx.x, y = threadIdx.y;
    #pragma unroll
    for (int dy=0; dy<32; dy+=8)
        tile[y+dy][x] = in[(size_t)(r0+y+dy)*C + c0 + x];
    __syncthreads();
    #pragma unroll
    for (int dy=0; dy<32; dy+=8)
        out[(size_t)(c0+y+dy)*R + r0 + x] = tile[x][y+dy];
}

// =============================================================================
// init / finalize / log_softmax
// =============================================================================
__global__ void k_init(const float* __restrict__ eh){
    int idx = blockIdx.x*256 + threadIdx.x;           // 0..65535
    int k = idx & (H_-1), b = (idx >> 10) & 31, l = idx >> 15;
    (l ? g_h1T[0] : g_h0T[0])[(size_t)k*B_ + b] = eh[idx];
}

__global__ void k_final(float* __restrict__ dst){
    int idx = blockIdx.x*256 + threadIdx.x;
    int k = idx & (H_-1), b = (idx >> 10) & 31, l = idx >> 15;
    dst[idx] = (l ? g_h1T[0] : g_h0T[0])[(size_t)k*B_ + b];   // parity 0 after 64 steps
}

__global__ __launch_bounds__(256) void k_lsm(float* __restrict__ out){
    float* p = out + (size_t)blockIdx.x * V_;
    __shared__ float red[256];
    float m = -3.4e38f;
    for (int i = threadIdx.x; i < V_; i += 256) m = fmaxf(m, p[i]);
    red[threadIdx.x] = m; __syncthreads();
    for (int s=128; s; s>>=1){
        if (threadIdx.x < s) red[threadIdx.x] = fmaxf(red[threadIdx.x], red[threadIdx.x+s]);
        __syncthreads();
    }
    m = red[0]; __syncthreads();
    float sum = 0.f;
    for (int i = threadIdx.x; i < V_; i += 256) sum += __expf(p[i] - m);
    red[threadIdx.x] = sum; __syncthreads();
    for (int s=128; s; s>>=1){
        if (threadIdx.x < s) red[threadIdx.x] += red[threadIdx.x+s];
        __syncthreads();
    }
    float lse = m + logf(red[0]);
    for (int i = threadIdx.x; i < V_; i += 256) p[i] -= lse;
}

// =============================================================================
extern "C" void kernel_launch(void* const* d_in, const int* in_sizes, int n_in,
                              void* d_out, int out_size) {
    const float* eh   = (const float*)d_in[1];   // encoder_hidden [2,32,1024]
    const float* emb  = (const float*)d_in[2];   // embedding [V,E]
    const float* wih0 = (const float*)d_in[3];
    const float* whh0 = (const float*)d_in[4];
    const float* bih0 = (const float*)d_in[5];
    const float* bhh0 = (const float*)d_in[6];
    const float* wih1 = (const float*)d_in[7];
    const float* whh1 = (const float*)d_in[8];
    const float* bih1 = (const float*)d_in[9];
    const float* bhh1 = (const float*)d_in[10];
    const float* wout = (const float*)d_in[11];
    const float* bout = (const float*)d_in[12];

    float* out  = (float*)d_out;                 // [B,T,V] log-softmax
    float* hfin = out + (size_t)B_*T_*V_;        // [2,B,H]

    // per-replay weight prep (amortized over 64 steps)
    dim3 tb(32,8);
    k_transpose<<<dim3(E_/32, G3_/32), tb>>>(wih0, G3_, E_, 0);
    k_transpose<<<dim3(H_/32, G3_/32), tb>>>(whh0, G3_, H_, 1);
    k_transpose<<<dim3(H_/32, G3_/32), tb>>>(wih1, G3_, H_, 2);
    k_transpose<<<dim3(H_/32, G3_/32), tb>>>(whh1, G3_, H_, 3);
    k_wsplit<<<(VT_*8*KT_*32)/256, 256>>>(wout);

    k_init<<<256,256>>>(eh);
    for (int t=0; t<T_; t++){
        const int p = t & 1;
        // layer 0: gi = emb[tok] @ wih0^T (gather), gh = h0_old @ whh0^T
        k_gates<<<NJ_GATES*SPLITK*2,256>>>(0, 0, 1, t, p, emb);
        k_combine<<<H_*B_/256,256>>>(bih0, bhh0, p, 1-p, 0);
        // layer 1: gi = h0_new @ wih1^T, gh = h1_old @ whh1^T
        k_gates<<<NJ_GATES*SPLITK*2,256>>>(1, 1-p, 0, t, 2+p, emb);
        k_combine<<<H_*B_/256,256>>>(bih1, bhh1, 2+p, 3-p, 1);  // + h frags + argmax reset
        // logits on HMMA tensor path + fused argmax from h1_new
        k_logits_mma<<<VT_, 256>>>(bout, out, t);
    }
    k_final<<<256,256>>>(hfin);
    k_lsm<<<B_*T_,256>>>(out);
}

// round 14
// speedup vs baseline: 1.9672x; 1.0593x over previous
#include <cuda_runtime.h>
#include <cuda_bf16.h>
#include <cstdint>

#define B_   32
#define T_   64
#define E_   512
#define H_   1024
#define V_   32000
#define G3_  3072
#define SOS_ 1
#define SPG  6        // gates split-K
#define VT_  250      // vocab tiles of 128
#define KT_  64       // logits K tiles of 16

// gate weight fragment offsets (uint4 units): [jt*8+mt][ktile][lane]
#define OFF_WIH0 0            // KT=32: 24*8*32*32 = 196608
#define OFF_WHH0 196608       // KT=64: 393216
#define OFF_WIH1 589824
#define OFF_WHH1 983040
#define GWF_TOT  1376256

// ---------------- persistent device state ----------------
__device__ float g_h0T[2][H_*B_];            // fp32 hidden, transposed [k][b], ping-pong
__device__ float g_h1T[2][H_*B_];
__device__ float g_giP[SPG][G3_*B_];         // split-K partials, layout [j][b]
__device__ float g_ghP[SPG][G3_*B_];
__device__ unsigned long long g_argmax[B_];  // packed (orderable_val<<32 | ~index)

// logits w_out bf16 hi/lo A-fragments: ((vt*8+mt)*KT_+kt)*32+lane -> uint4
__device__ uint4 g_wfHi[(size_t)VT_*8*KT_*32];
__device__ uint4 g_wfLo[(size_t)VT_*8*KT_*32];
// gate weight A-fragments
__device__ uint4 g_gwfHi[GWF_TOT];
__device__ uint4 g_gwfLo[GWF_TOT];
// B-fragments (activations) hi/lo: code 0=x(emb), 1/2=h0 parity, 3/4=h1 parity
// entry (kt*4+nt)*32+lane -> uint2 ; max KT=64
__device__ uint2 g_bfHi[5][64*4*32];
__device__ uint2 g_bfLo[5][64*4*32];

__device__ __forceinline__ float* hbuf(int code){
    switch(code){
        case 0:  return g_h0T[0];
        case 1:  return g_h0T[1];
        case 2:  return g_h1T[0];
        default: return g_h1T[1];
    }
}

__device__ __forceinline__ unsigned long long packv(float f, unsigned v){
    unsigned u = __float_as_uint(f);
    u = (u & 0x80000000u) ? ~u : (u | 0x80000000u);   // monotonic order-preserving map
    return ((unsigned long long)u << 32) | (unsigned long long)(0xFFFFFFFFu - v);
}

// baseline-sm_103 HMMA: m16n8k16 bf16 -> f32, accumulate in place
__device__ __forceinline__ void mma16816(float* d, const uint32_t* a, const uint32_t* b){
    asm volatile("mma.sync.aligned.m16n8k16.row.col.f32.bf16.bf16.f32 "
        "{%0,%1,%2,%3}, {%4,%5,%6,%7}, {%8,%9}, {%0,%1,%2,%3};"
        : "+f"(d[0]), "+f"(d[1]), "+f"(d[2]), "+f"(d[3])
        : "r"(a[0]), "r"(a[1]), "r"(a[2]), "r"(a[3]), "r"(b[0]), "r"(b[1]));
}

// write one activation value into B-fragment hi/lo layout (validated in R13)
__device__ __forceinline__ void write_bfrag(int code, int k, int b, float hv){
    __nv_bfloat16 hi = __float2bfloat16(hv);
    __nv_bfloat16 lo = __float2bfloat16(hv - __bfloat162float(hi));
    int ktile = k >> 4, kin = k & 15;
    int reg = kin >> 3, c = kin & 7;
    int lane = (b & 7)*4 + (c >> 1);
    int ntile = b >> 3;
    int half = c & 1;
    size_t off = ((size_t)(ktile*4 + ntile)*32 + lane)*4 + reg*2 + half; // ushort units
    ((unsigned short*)g_bfHi[code])[off] = __bfloat16_as_ushort(hi);
    ((unsigned short*)g_bfLo[code])[off] = __bfloat16_as_ushort(lo);
}

// =============================================================================
// Gates GEMM via HMMA hi/lo: partials[j][b] = sum_k W[j,k]*a[k,b]
// grid = 24 jtiles x {gi,gh} x SPG ; block 256 thr (8 warps x 16 j-rows)
// =============================================================================
__global__ __launch_bounds__(256) void k_gates_mma(int layer, int gi_code, int gh_code)
{
    const int tid = threadIdx.x, wid = tid >> 5, lane = tid & 31;
    const int bid = blockIdx.x;
    const int is_gh = (bid >= 24*SPG);
    const int rem = is_gh ? bid - 24*SPG : bid;
    const int s = rem / 24, jt = rem % 24;

    int KT, matOff;
    if (layer == 0){
        if (is_gh){ KT = 64; matOff = OFF_WHH0; }
        else      { KT = 32; matOff = OFF_WIH0; }
    } else {
        if (is_gh){ KT = 64; matOff = OFF_WHH1; }
        else      { KT = 64; matOff = OFF_WIH1; }
    }
    const int bcode = is_gh ? gh_code : gi_code;
    const uint2* __restrict__ bHi = g_bfHi[bcode];
    const uint2* __restrict__ bLo = g_bfLo[bcode];
    float* __restrict__ out = is_gh ? g_ghP[s] : g_giP[s];

    const int kt0 = (KT * s) / SPG;
    const int kt1 = (KT * (s+1)) / SPG;

    const uint4* __restrict__ aHi = g_gwfHi + matOff + ((size_t)(jt*8 + wid)*KT)*32 + lane;
    const uint4* __restrict__ aLo = g_gwfLo + matOff + ((size_t)(jt*8 + wid)*KT)*32 + lane;

    float acc[4][4];
    #pragma unroll
    for (int n=0;n<4;n++){ acc[n][0]=0.f; acc[n][1]=0.f; acc[n][2]=0.f; acc[n][3]=0.f; }

    uint4 ah = aHi[(size_t)kt0*32], al = aLo[(size_t)kt0*32];
    for (int kt = kt0; kt < kt1; kt++){
        uint4 ah_n, al_n;
        if (kt+1 < kt1){ ah_n = aHi[(size_t)(kt+1)*32]; al_n = aLo[(size_t)(kt+1)*32]; }
        uint2 bh[4], bl[4];
        #pragma unroll
        for (int nt=0; nt<4; nt++){
            bh[nt] = bHi[(kt*4 + nt)*32 + lane];
            bl[nt] = bLo[(kt*4 + nt)*32 + lane];
        }
        #pragma unroll
        for (int nt=0; nt<4; nt++){
            mma16816(acc[nt], (const uint32_t*)&ah, (const uint32_t*)&bh[nt]);
            mma16816(acc[nt], (const uint32_t*)&ah, (const uint32_t*)&bl[nt]);
            mma16816(acc[nt], (const uint32_t*)&al, (const uint32_t*)&bh[nt]);
        }
        ah = ah_n; al = al_n;
    }

    const int g  = lane >> 2, c0 = (lane & 3)*2;
    const int j0 = jt*128 + wid*16 + g;
    #pragma unroll
    for (int nt=0; nt<4; nt++){
        const int b = nt*8 + c0;
        out[(size_t)j0     *B_ + b    ] = acc[nt][0];
        out[(size_t)j0     *B_ + b + 1] = acc[nt][1];
        out[(size_t)(j0+8) *B_ + b    ] = acc[nt][2];
        out[(size_t)(j0+8) *B_ + b + 1] = acc[nt][3];
    }
}

// =============================================================================
// GRU combine: sums split-K partials, writes fp32 h + bf16 hi/lo B-fragments
// =============================================================================
__global__ __launch_bounds__(256) void k_combine(
    const float* __restrict__ bih, const float* __restrict__ bhh,
    int code_old, int code_new, int fragcode, int reset)
{
    int idx = blockIdx.x*256 + threadIdx.x;   // 0..32767
    int b = idx & 31, k = idx >> 5;
    float gr=0.f, gz=0.f, gn=0.f, hr=0.f, hz=0.f, hn=0.f;
    #pragma unroll
    for (int s=0;s<SPG;s++){
        gr += g_giP[s][(size_t)k*B_ + b];
        gz += g_giP[s][(size_t)(H_  +k)*B_ + b];
        gn += g_giP[s][(size_t)(2*H_+k)*B_ + b];
        hr += g_ghP[s][(size_t)k*B_ + b];
        hz += g_ghP[s][(size_t)(H_  +k)*B_ + b];
        hn += g_ghP[s][(size_t)(2*H_+k)*B_ + b];
    }
    float r = 1.f/(1.f + expf(-(gr + bih[k]     + hr + bhh[k])));
    float z = 1.f/(1.f + expf(-(gz + bih[H_+k]  + hz + bhh[H_+k])));
    float n = tanhf(gn + bih[2*H_+k] + r*(hn + bhh[2*H_+k]));
    float h = hbuf(code_old)[(size_t)k*B_ + b];
    float hv = (1.f - z)*n + z*h;
    hbuf(code_new)[(size_t)k*B_ + b] = hv;
    write_bfrag(fragcode, k, b, hv);
    if (reset && idx < B_) g_argmax[idx] = 0ULL;
}

// =============================================================================
// embedding gather -> B-fragments (code 0), runs after previous step's argmax
// =============================================================================
__global__ __launch_bounds__(256) void k_embfrag(const float* __restrict__ emb, int t)
{
    int idx = blockIdx.x*256 + threadIdx.x;   // 0..16383
    int k = idx & (E_-1), b = idx >> 9;
    int tok = SOS_;
    if (t > 0) tok = (int)(0xFFFFFFFFu - (unsigned)(g_argmax[b] & 0xFFFFFFFFull));
    float x = emb[(size_t)tok*E_ + k];
    write_bfrag(0, k, b, x);
}

// =============================================================================
// w_out -> bf16 hi/lo per-lane A-fragments (once per replay)
// =============================================================================
__global__ __launch_bounds__(256) void k_wsplit(const float* __restrict__ w){
    size_t gid = (size_t)blockIdx.x*256 + threadIdx.x;  // 250*8*64*32 = 4,096,000
    int lane  = (int)(gid & 31);
    int ktile = (int)((gid >> 5) & 63);
    int mtile = (int)((gid >> 11) & 7);
    int vt    = (int)(gid >> 14);
    int g  = lane >> 2, c0 = (lane & 3)*2;
    int v0 = vt*128 + mtile*16;
    int k0 = ktile*16;
    uint32_t hi[4], lo[4];
    #pragma unroll
    for (int r=0;r<4;r++){
        int row = v0 + g + (r & 1)*8;
        int col = k0 + c0 + (r >> 1)*8;
        float x0 = w[(size_t)row*H_ + col];
        float x1 = w[(size_t)row*H_ + col + 1];
        __nv_bfloat16 h0 = __float2bfloat16(x0), h1 = __float2bfloat16(x1);
        __nv_bfloat16 l0 = __float2bfloat16(x0 - __bfloat162float(h0));
        __nv_bfloat16 l1 = __float2bfloat16(x1 - __bfloat162float(h1));
        hi[r] = (uint32_t)__bfloat16_as_ushort(h0) | ((uint32_t)__bfloat16_as_ushort(h1) << 16);
        lo[r] = (uint32_t)__bfloat16_as_ushort(l0) | ((uint32_t)__bfloat16_as_ushort(l1) << 16);
    }
    g_wfHi[gid] = make_uint4(hi[0], hi[1], hi[2], hi[3]);
    g_wfLo[gid] = make_uint4(lo[0], lo[1], lo[2], lo[3]);
}

// gate weight W[G3_][K] -> A-fragments at g_gwf + matOff (once per replay)
__global__ __launch_bounds__(256) void k_wsplit_g(const float* __restrict__ w, int K, int matOff){
    size_t gid = (size_t)blockIdx.x*256 + threadIdx.x;  // 24*8*(K/16)*32 threads
    const int KT = K >> 4;
    int lane  = (int)(gid & 31);
    int ktile = (int)((gid >> 5) % KT);
    int mt    = (int)((gid >> 5) / KT);   // 0..191 = jt*8+mtile
    int g  = lane >> 2, c0 = (lane & 3)*2;
    int j0 = mt*16;
    int k0 = ktile*16;
    uint32_t hi[4], lo[4];
    #pragma unroll
    for (int r=0;r<4;r++){
        int row = j0 + g + (r & 1)*8;
        int col = k0 + c0 + (r >> 1)*8;
        float x0 = w[(size_t)row*K + col];
        float x1 = w[(size_t)row*K + col + 1];
        __nv_bfloat16 h0 = __float2bfloat16(x0), h1 = __float2bfloat16(x1);
        __nv_bfloat16 l0 = __float2bfloat16(x0 - __bfloat162float(h0));
        __nv_bfloat16 l1 = __float2bfloat16(x1 - __bfloat162float(h1));
        hi[r] = (uint32_t)__bfloat16_as_ushort(h0) | ((uint32_t)__bfloat16_as_ushort(h1) << 16);
        lo[r] = (uint32_t)__bfloat16_as_ushort(l0) | ((uint32_t)__bfloat16_as_ushort(l1) << 16);
    }
    g_gwfHi[matOff + gid] = make_uint4(hi[0], hi[1], hi[2], hi[3]);
    g_gwfLo[matOff + gid] = make_uint4(lo[0], lo[1], lo[2], lo[3]);
}

// =============================================================================
// Logits via mma.sync bf16 hi/lo (3 cross terms) + bias + fused argmax.
// =============================================================================
__global__ __launch_bounds__(256,3) void k_logits_mma(
    const float* __restrict__ bout, float* __restrict__ out, int t, int bcode)
{
    __shared__ unsigned long long red[8][32];

    const int tid = threadIdx.x, wid = tid >> 5, lane = tid & 31;
    const int vt  = blockIdx.x;

    float acc[4][4];
    #pragma unroll
    for (int n=0;n<4;n++){ acc[n][0]=0.f; acc[n][1]=0.f; acc[n][2]=0.f; acc[n][3]=0.f; }

    const uint4* __restrict__ aHi = g_wfHi + ((size_t)(vt*8 + wid)*KT_)*32 + lane;
    const uint4* __restrict__ aLo = g_wfLo + ((size_t)(vt*8 + wid)*KT_)*32 + lane;
    const uint2* __restrict__ bHi = g_bfHi[bcode];
    const uint2* __restrict__ bLo = g_bfLo[bcode];

    uint4 ah = aHi[0], al = aLo[0];
    for (int kt = 0; kt < KT_; kt++){
        uint4 ah_n, al_n;
        if (kt < KT_-1){ ah_n = aHi[(kt+1)*32]; al_n = aLo[(kt+1)*32]; }
        uint2 bh[4], bl[4];
        #pragma unroll
        for (int nt=0; nt<4; nt++){
            bh[nt] = bHi[(kt*4 + nt)*32 + lane];
            bl[nt] = bLo[(kt*4 + nt)*32 + lane];
        }
        #pragma unroll
        for (int nt=0; nt<4; nt++){
            mma16816(acc[nt], (const uint32_t*)&ah, (const uint32_t*)&bh[nt]);
            mma16816(acc[nt], (const uint32_t*)&ah, (const uint32_t*)&bl[nt]);
            mma16816(acc[nt], (const uint32_t*)&al, (const uint32_t*)&bh[nt]);
        }
        ah = ah_n; al = al_n;
    }

    const int g  = lane >> 2, c0 = (lane & 3)*2;
    const int v0 = vt*128 + wid*16 + g;
    const float bias0 = bout[v0], bias1 = bout[v0 + 8];

    unsigned long long colmax[8];
    #pragma unroll
    for (int nt=0; nt<4; nt++){
        const int b = nt*8 + c0;
        float v00 = acc[nt][0] + bias0;
        float v01 = acc[nt][1] + bias0;
        float v10 = acc[nt][2] + bias1;
        float v11 = acc[nt][3] + bias1;
        out[((size_t)b    *T_ + t)*V_ + v0    ] = v00;
        out[((size_t)(b+1)*T_ + t)*V_ + v0    ] = v01;
        out[((size_t)b    *T_ + t)*V_ + v0 + 8] = v10;
        out[((size_t)(b+1)*T_ + t)*V_ + v0 + 8] = v11;
        unsigned long long p0 = packv(v00, (unsigned)v0);
        unsigned long long q0 = packv(v10, (unsigned)(v0+8));
        unsigned long long p1 = packv(v01, (unsigned)v0);
        unsigned long long q1 = packv(v11, (unsigned)(v0+8));
        colmax[nt*2]   = p0 > q0 ? p0 : q0;
        colmax[nt*2+1] = p1 > q1 ? p1 : q1;
    }
    #pragma unroll
    for (int q=0;q<8;q++){
        #pragma unroll
        for (int off=4; off<32; off<<=1){
            unsigned long long o = __shfl_xor_sync(0xFFFFFFFFu, colmax[q], off);
            if (o > colmax[q]) colmax[q] = o;
        }
    }
    if (lane < 4){
        #pragma unroll
        for (int nt=0; nt<4; nt++){
            red[wid][nt*8 + lane*2    ] = colmax[nt*2];
            red[wid][nt*8 + lane*2 + 1] = colmax[nt*2+1];
        }
    }
    __syncthreads();
    if (tid < B_){
        unsigned long long m = red[0][tid];
        #pragma unroll
        for (int w=1; w<8; w++) if (red[w][tid] > m) m = red[w][tid];
        atomicMax(&g_argmax[tid], m);
    }
}

// =============================================================================
// init / finalize / log_softmax
// =============================================================================
__global__ void k_init(const float* __restrict__ eh){
    int idx = blockIdx.x*256 + threadIdx.x;           // 0..65535
    int k = idx & (H_-1), b = (idx >> 10) & 31, l = idx >> 15;
    float v = eh[idx];
    (l ? g_h1T[0] : g_h0T[0])[(size_t)k*B_ + b] = v;
    write_bfrag(l ? 3 : 1, k, b, v);                  // parity-0 fragment buffers
}

__global__ void k_final(float* __restrict__ dst){
    int idx = blockIdx.x*256 + threadIdx.x;
    int k = idx & (H_-1), b = (idx >> 10) & 31, l = idx >> 15;
    dst[idx] = (l ? g_h1T[0] : g_h0T[0])[(size_t)k*B_ + b];   // parity 0 after 64 steps
}

__global__ __launch_bounds__(256) void k_lsm(float* __restrict__ out){
    float* p = out + (size_t)blockIdx.x * V_;
    __shared__ float red[256];
    float m = -3.4e38f;
    for (int i = threadIdx.x; i < V_; i += 256) m = fmaxf(m, p[i]);
    red[threadIdx.x] = m; __syncthreads();
    for (int s=128; s; s>>=1){
        if (threadIdx.x < s) red[threadIdx.x] = fmaxf(red[threadIdx.x], red[threadIdx.x+s]);
        __syncthreads();
    }
    m = red[0]; __syncthreads();
    float sum = 0.f;
    for (int i = threadIdx.x; i < V_; i += 256) sum += __expf(p[i] - m);
    red[threadIdx.x] = sum; __syncthreads();
    for (int s=128; s; s>>=1){
        if (threadIdx.x < s) red[threadIdx.x] += red[threadIdx.x+s];
        __syncthreads();
    }
    float lse = m + logf(red[0]);
    for (int i = threadIdx.x; i < V_; i += 256) p[i] -= lse;
}

// =============================================================================
extern "C" void kernel_launch(void* const* d_in, const int* in_sizes, int n_in,
                              void* d_out, int out_size) {
    const float* eh   = (const float*)d_in[1];   // encoder_hidden [2,32,1024]
    const float* emb  = (const float*)d_in[2];   // embedding [V,E]
    const float* wih0 = (const float*)d_in[3];
    const float* whh0 = (const float*)d_in[4];
    const float* bih0 = (const float*)d_in[5];
    const float* bhh0 = (const float*)d_in[6];
    const float* wih1 = (const float*)d_in[7];
    const float* whh1 = (const float*)d_in[8];
    const float* bih1 = (const float*)d_in[9];
    const float* bhh1 = (const float*)d_in[10];
    const float* wout = (const float*)d_in[11];
    const float* bout = (const float*)d_in[12];

    float* out  = (float*)d_out;                 // [B,T,V] log-softmax
    float* hfin = out + (size_t)B_*T_*V_;        // [2,B,H]

    // per-replay weight prep (amortized over 64 steps)
    k_wsplit<<<(VT_*8*KT_*32)/256, 256>>>(wout);
    k_wsplit_g<<<(24*8*(E_/16)*32)/256, 256>>>(wih0, E_, OFF_WIH0);
    k_wsplit_g<<<(24*8*(H_/16)*32)/256, 256>>>(whh0, H_, OFF_WHH0);
    k_wsplit_g<<<(24*8*(H_/16)*32)/256, 256>>>(wih1, H_, OFF_WIH1);
    k_wsplit_g<<<(24*8*(H_/16)*32)/256, 256>>>(whh1, H_, OFF_WHH1);

    k_init<<<256,256>>>(eh);
    for (int t=0; t<T_; t++){
        const int p = t & 1;
        // embedding gather (token from argmax of step t-1) -> B-fragments code 0
        k_embfrag<<<B_*E_/256,256>>>(emb, t);
        // layer 0: gi = x @ wih0^T (B=code0), gh = h0_old @ whh0^T (B=code 1+p)
        k_gates_mma<<<24*SPG*2,256>>>(0, 0, 1+p);
        k_combine<<<H_*B_/256,256>>>(bih0, bhh0, p, 1-p, 1+(1-p), 0);
        // layer 1: gi = h0_new (code 1+(1-p)), gh = h1_old (code 3+p)
        k_gates_mma<<<24*SPG*2,256>>>(1, 1+(1-p), 3+p);
        k_combine<<<H_*B_/256,256>>>(bih1, bhh1, 2+p, 3-p, 3+(1-p), 1);  // + argmax reset
        // logits from h1_new (code 3+(1-p)) + fused argmax
        k_logits_mma<<<VT_,256>>>(bout, out, t, 3+(1-p));
    }
    k_final<<<256,256>>>(hfin);
    k_lsm<<<B_*T_,256>>>(out);
}